// round 6
// baseline (speedup 1.0000x reference)
#include <cuda_runtime.h>
#include <cuda_bf16.h>

// SST: sst[b, k(b,f,t), t] += coeffs[b,f,t], k = clip(f + adj, 0, F-1),
// adj = signbit(x[t+1]) - signbit(x[t]) in {-1,0,+1} (adj=0 at t=T-1).
// k in {f-1, f, f+1} -> scatter re-expressed as rolling gather along F with
// three register accumulators (rows f-1, f, f+1). 8-stage cp.async SMEM ring
// covers DRAM latency independent of register pressure / occupancy.
//
// R6 (bench is pinned at the steady-state HBM roofline -> cut traffic):
//  - NSEG 8->4: ghost rows per batch 14->6 (reads -1.5% of total traffic).
//    Pipeline keeps ~96KB/SM of reads in flight, so the lower occupancy of
//    1024 CTAs no longer matters (it did in the unpiped R2 variant).
//  - output stores use st.global.cs (evict-first): write-once-dead lines stop
//    evicting input from L2, so ghost rereads / replay reuse hit L2.

constexpr int Bdim = 16;
constexpr int Fdim = 256;
constexpr int Tdim = 8192;
constexpr int TPB  = 128;
constexpr int NSEG = 4;
constexpr int SEG  = Fdim / NSEG;      // 64 output rows per CTA
constexpr int NR   = SEG + 2;          // rows touched incl. ghosts = 66
constexpr int NST  = 8;                // pipeline stages
constexpr int CHUNK = TPB * 16;        // 2048 B of row data per CTA
constexpr int STAGE = CHUNK + 32;      // +16B neighbor tail +16B pad = 2080

__device__ __forceinline__ int sgnbit(float x) {
    return (int)(__float_as_uint(x) >> 31);   // matches angle(): pi iff sign bit
}

__device__ __forceinline__ void stg_cs(float* p, const float4& v) {
    asm volatile("st.global.cs.v4.f32 [%0], {%1, %2, %3, %4};"
                 :: "l"(p), "f"(v.x), "f"(v.y), "f"(v.z), "f"(v.w) : "memory");
}

__global__ __launch_bounds__(TPB, 13)
void sst_pipe_kernel(const float* __restrict__ in, float* __restrict__ out) {
    __shared__ __align__(16) unsigned char smbuf[NST * STAGE];

    const int tid = threadIdx.x;
    const int t0  = (blockIdx.x * TPB + tid) * 4;
    const int b   = blockIdx.y;
    const int fs  = blockIdx.z * SEG;
    const bool notlast = (t0 + 4) < Tdim;                        // per-thread
    const bool has_tail = (blockIdx.x + 1) * (CHUNK / 4) < Tdim; // per-CTA

    const size_t bofs = (size_t)b * Fdim * Tdim;
    const float* __restrict__ gbase = in + bofs + (size_t)blockIdx.x * (CHUNK / 4);
    float* __restrict__ obase = out + bofs + t0;

    const unsigned smem0 = (unsigned)__cvta_generic_to_shared(smbuf);

    // producer: one 16B cp.async per thread (+16B tail via tid 0) for row r;
    // ALWAYS commits a group (possibly empty) so group counting is uniform.
    auto issue = [&](int r) {
        const int f = fs - 1 + r;
        if (r < NR && (unsigned)f < (unsigned)Fdim) {
            const float* src = gbase + (size_t)f * Tdim;
            const unsigned dst = smem0 + (r % NST) * STAGE;
            asm volatile("cp.async.cg.shared.global [%0], [%1], 16;"
                         :: "r"(dst + tid * 16), "l"(src + tid * 4) : "memory");
            if (tid == 0 && has_tail) {
                asm volatile("cp.async.cg.shared.global [%0], [%1], 16;"
                             :: "r"(dst + CHUNK), "l"(src + CHUNK / 4) : "memory");
            }
        }
        asm volatile("cp.async.commit_group;" ::: "memory");
    };

    // make row r resident for all threads, then refill one slot.
    // commits before acquire(r) = (NST-1) + r; need rows 0..r done (r+1
    // groups) -> pending = NST-2. Holds for ALL r (empty tail commits).
    auto acquire = [&](int r) {
        asm volatile("cp.async.wait_group %0;" :: "n"(NST - 2) : "memory");
        __syncthreads();
        issue(r + NST - 1);
    };

    // read row r from SMEM: values + per-element shifts d in {-1,0,+1}
    auto load_row = [&](int r, float4& v, int& d0, int& d1, int& d2, int& d3) {
        const unsigned char* p = smbuf + (r % NST) * STAGE + tid * 16;
        v = *reinterpret_cast<const float4*>(p);
        const float nx = *reinterpret_cast<const float*>(p + 16);
        const int s0 = sgnbit(v.x), s1 = sgnbit(v.y);
        const int s2 = sgnbit(v.z), s3 = sgnbit(v.w);
        const int s4 = sgnbit(nx);
        d0 = s1 - s0; d1 = s2 - s1; d2 = s3 - s2;
        d3 = notlast ? (s4 - s3) : 0;   // pad: adj=0 at t=T-1
    };

    // ---- pipeline prologue: rows 0..NST-2 ----
    #pragma unroll
    for (int r = 0; r < NST - 1; ++r) issue(r);

    const float4 z = make_float4(0.f, 0.f, 0.f, 0.f);
    float4 A, B = z, C = z;
    float4 v;
    int d0, d1, d2, d3;

    // ---- r=0: lower ghost row (f = fs-1) -> only its up-moves land in B ----
    acquire(0);
    if (fs > 0) {   // block-uniform
        load_row(0, v, d0, d1, d2, d3);
        B.x += (d0 > 0) ? v.x : 0.f;
        B.y += (d1 > 0) ? v.y : 0.f;
        B.z += (d2 > 0) ? v.z : 0.f;
        B.w += (d3 > 0) ? v.w : 0.f;
    }

    // ---- r=1: first interior row f = fs (holds the f==0 clamp) ----
    acquire(1);
    load_row(1, v, d0, d1, d2, d3);
    if (fs == 0) {   // clip at lower F edge: down-moves stay in row 0
        d0 = max(d0, 0); d1 = max(d1, 0); d2 = max(d2, 0); d3 = max(d3, 0);
    }
    // A-part (out[fs-1]) belongs to the neighbor block: discard.
    B.x += (d0 == 0) ? v.x : 0.f;  C.x += (d0 > 0) ? v.x : 0.f;
    B.y += (d1 == 0) ? v.y : 0.f;  C.y += (d1 > 0) ? v.y : 0.f;
    B.z += (d2 == 0) ? v.z : 0.f;  C.z += (d2 > 0) ? v.z : 0.f;
    B.w += (d3 == 0) ? v.w : 0.f;  C.w += (d3 > 0) ? v.w : 0.f;

    // ---- r=2..SEG-1: branch-free interior (f = fs+1 .. fs+SEG-2) ----
    float* orow = obase + (size_t)fs * Tdim;
    #pragma unroll 2
    for (int r = 2; r < SEG; ++r) {
        acquire(r);
        A = B; B = C; C = z;
        load_row(r, v, d0, d1, d2, d3);
        A.x += (d0 < 0) ? v.x : 0.f;
        B.x += (d0 == 0) ? v.x : 0.f;
        C.x += (d0 > 0) ? v.x : 0.f;
        A.y += (d1 < 0) ? v.y : 0.f;
        B.y += (d1 == 0) ? v.y : 0.f;
        C.y += (d1 > 0) ? v.y : 0.f;
        A.z += (d2 < 0) ? v.z : 0.f;
        B.z += (d2 == 0) ? v.z : 0.f;
        C.z += (d2 > 0) ? v.z : 0.f;
        A.w += (d3 < 0) ? v.w : 0.f;
        B.w += (d3 == 0) ? v.w : 0.f;
        C.w += (d3 > 0) ? v.w : 0.f;
        stg_cs(orow, A);                        // out[f-1] complete
        orow += Tdim;
    }

    // ---- r=SEG: last interior row f = fs+SEG-1 (holds the f==F-1 clamp) ----
    acquire(SEG);
    A = B; B = C;
    load_row(SEG, v, d0, d1, d2, d3);
    if (fs + SEG == Fdim) {   // clip at upper F edge: up-moves stay
        d0 = min(d0, 0); d1 = min(d1, 0); d2 = min(d2, 0); d3 = min(d3, 0);
    }
    // C-part (out[fs+SEG]) belongs to the neighbor block: discard.
    A.x += (d0 < 0) ? v.x : 0.f;  B.x += (d0 == 0) ? v.x : 0.f;
    A.y += (d1 < 0) ? v.y : 0.f;  B.y += (d1 == 0) ? v.y : 0.f;
    A.z += (d2 < 0) ? v.z : 0.f;  B.z += (d2 == 0) ? v.z : 0.f;
    A.w += (d3 < 0) ? v.w : 0.f;  B.w += (d3 == 0) ? v.w : 0.f;
    stg_cs(orow, A);                            // out[fs+SEG-2]
    orow += Tdim;

    // ---- r=SEG+1: upper ghost row f = fs+SEG -> only its down-moves in B ----
    acquire(SEG + 1);
    if (fs + SEG < Fdim) {   // block-uniform
        load_row(SEG + 1, v, d0, d1, d2, d3);
        B.x += (d0 < 0) ? v.x : 0.f;
        B.y += (d1 < 0) ? v.y : 0.f;
        B.z += (d2 < 0) ? v.z : 0.f;
        B.w += (d3 < 0) ? v.w : 0.f;
    }
    stg_cs(orow, B);                            // out[fs+SEG-1] complete
}

extern "C" void kernel_launch(void* const* d_in, const int* in_sizes, int n_in,
                              void* d_out, int out_size) {
    const float* coeffs = (const float*)d_in[0];
    float* out = (float*)d_out;

    dim3 grid(Tdim / 4 / TPB, Bdim, NSEG);   // (16, 16, 4) = 1024 CTAs
    dim3 block(TPB);
    sst_pipe_kernel<<<grid, block>>>(coeffs, out);
}

// round 7
// speedup vs baseline: 1.0812x; 1.0812x over previous
#include <cuda_runtime.h>
#include <cuda_bf16.h>

// SST: sst[b, k(b,f,t), t] += coeffs[b,f,t], k = clip(f + adj, 0, F-1),
// adj = signbit(x[t+1]) - signbit(x[t]) in {-1,0,+1} (adj=0 at t=T-1).
// k in {f-1, f, f+1} -> scatter re-expressed as rolling gather along F with
// three register accumulators (rows f-1, f, f+1). cp.async SMEM ring covers
// DRAM latency independent of register pressure.
//
// R7 (revert R6's NSEG=4 + st.cs regression; attack barrier overhead):
//  - NSEG=8, plain stores (R5 config, the validated best pipeline variant).
//  - TWO rows per pipeline stage: 17 acquires per CTA instead of 34 ->
//    half the __syncthreads + wait_group drains, better load batching
//    between barriers. Ring = 8 row slots = 4 pairs, 3 pairs in flight.
//  - Commit groups counted uniformly (empty commits at the tail; R4 lesson).

constexpr int Bdim = 16;
constexpr int Fdim = 256;
constexpr int Tdim = 8192;
constexpr int TPB  = 128;
constexpr int NSEG = 8;
constexpr int SEG  = Fdim / NSEG;      // 32 output rows per CTA
constexpr int NR   = SEG + 2;          // rows touched incl. ghosts = 34
constexpr int NPAIR = NR / 2;          // 17 two-row stages
constexpr int NSLOT = 8;               // ring of 8 row slots = 4 pairs
constexpr int CHUNK = TPB * 16;        // 2048 B of row data per CTA
constexpr int STAGE = CHUNK + 32;      // +16B neighbor tail +16B pad = 2080

__device__ __forceinline__ int sgnbit(float x) {
    return (int)(__float_as_uint(x) >> 31);   // matches angle(): pi iff sign bit
}

__global__ __launch_bounds__(TPB, 13)
void sst_pipe_kernel(const float* __restrict__ in, float* __restrict__ out) {
    __shared__ __align__(16) unsigned char smbuf[NSLOT * STAGE];

    const int tid = threadIdx.x;
    const int t0  = (blockIdx.x * TPB + tid) * 4;
    const int b   = blockIdx.y;
    const int fs  = blockIdx.z * SEG;
    const bool notlast = (t0 + 4) < Tdim;                        // per-thread
    const bool has_tail = (blockIdx.x + 1) * (CHUNK / 4) < Tdim; // per-CTA

    const size_t bofs = (size_t)b * Fdim * Tdim;
    const float* __restrict__ gbase = in + bofs + (size_t)blockIdx.x * (CHUNK / 4);
    float* __restrict__ obase = out + bofs + t0;

    const unsigned smem0 = (unsigned)__cvta_generic_to_shared(smbuf);

    // copy one row into its ring slot (16B per thread + 16B tail via tid 0)
    auto issue_row = [&](int r) {
        const int f = fs - 1 + r;
        if ((unsigned)f < (unsigned)Fdim) {
            const float* src = gbase + (size_t)f * Tdim;
            const unsigned dst = smem0 + (r % NSLOT) * STAGE;
            asm volatile("cp.async.cg.shared.global [%0], [%1], 16;"
                         :: "r"(dst + tid * 16), "l"(src + tid * 4) : "memory");
            if (tid == 0 && has_tail) {
                asm volatile("cp.async.cg.shared.global [%0], [%1], 16;"
                             :: "r"(dst + CHUNK), "l"(src + CHUNK / 4) : "memory");
            }
        }
    };

    // one commit group per PAIR; always commits (uniform group counting)
    auto issue_pair = [&](int p) {
        if (p < NPAIR) {
            issue_row(2 * p);
            issue_row(2 * p + 1);
        }
        asm volatile("cp.async.commit_group;" ::: "memory");
    };

    // make pair p resident for all threads, then refill one pair slot.
    // commits before acquire(p) = 3 + p; wait_group 2 -> p+1 pairs done.
    auto acquire = [&](int p) {
        asm volatile("cp.async.wait_group 2;" ::: "memory");
        __syncthreads();
        issue_pair(p + 3);
    };

    // read row r from SMEM: values + per-element shifts d in {-1,0,+1}
    auto load_row = [&](int r, float4& v, int& d0, int& d1, int& d2, int& d3) {
        const unsigned char* p = smbuf + (r % NSLOT) * STAGE + tid * 16;
        v = *reinterpret_cast<const float4*>(p);
        const float nx = *reinterpret_cast<const float*>(p + 16);
        const int s0 = sgnbit(v.x), s1 = sgnbit(v.y);
        const int s2 = sgnbit(v.z), s3 = sgnbit(v.w);
        const int s4 = sgnbit(nx);
        d0 = s1 - s0; d1 = s2 - s1; d2 = s3 - s2;
        d3 = notlast ? (s4 - s3) : 0;   // pad: adj=0 at t=T-1
    };

    // ---- pipeline prologue: pairs 0..2 (rows 0..5) ----
    issue_pair(0);
    issue_pair(1);
    issue_pair(2);

    const float4 z = make_float4(0.f, 0.f, 0.f, 0.f);
    float4 A, B = z, C = z;
    float4 v;
    int d0, d1, d2, d3;

    // ---- pair 0: lower ghost row (fs-1) + first interior row (fs) ----
    acquire(0);
    if (fs > 0) {   // ghost: only its up-moves land in out[fs] (B)
        load_row(0, v, d0, d1, d2, d3);
        B.x += (d0 > 0) ? v.x : 0.f;
        B.y += (d1 > 0) ? v.y : 0.f;
        B.z += (d2 > 0) ? v.z : 0.f;
        B.w += (d3 > 0) ? v.w : 0.f;
    }
    load_row(1, v, d0, d1, d2, d3);
    if (fs == 0) {   // clip at lower F edge: down-moves stay in row 0
        d0 = max(d0, 0); d1 = max(d1, 0); d2 = max(d2, 0); d3 = max(d3, 0);
    }
    // A-part (out[fs-1]) belongs to the neighbor block: discard.
    B.x += (d0 == 0) ? v.x : 0.f;  C.x += (d0 > 0) ? v.x : 0.f;
    B.y += (d1 == 0) ? v.y : 0.f;  C.y += (d1 > 0) ? v.y : 0.f;
    B.z += (d2 == 0) ? v.z : 0.f;  C.z += (d2 > 0) ? v.z : 0.f;
    B.w += (d3 == 0) ? v.w : 0.f;  C.w += (d3 > 0) ? v.w : 0.f;

    // ---- pairs 1..15: branch-free interior (rows 2..31 = f fs+1..fs+30) ----
    float* orow = obase + (size_t)fs * Tdim;
    #pragma unroll 1
    for (int p = 1; p < NPAIR - 1; ++p) {
        acquire(p);
        #pragma unroll
        for (int half = 0; half < 2; ++half) {
            const int r = 2 * p + half;
            A = B; B = C; C = z;
            load_row(r, v, d0, d1, d2, d3);
            A.x += (d0 < 0) ? v.x : 0.f;
            B.x += (d0 == 0) ? v.x : 0.f;
            C.x += (d0 > 0) ? v.x : 0.f;
            A.y += (d1 < 0) ? v.y : 0.f;
            B.y += (d1 == 0) ? v.y : 0.f;
            C.y += (d1 > 0) ? v.y : 0.f;
            A.z += (d2 < 0) ? v.z : 0.f;
            B.z += (d2 == 0) ? v.z : 0.f;
            C.z += (d2 > 0) ? v.z : 0.f;
            A.w += (d3 < 0) ? v.w : 0.f;
            B.w += (d3 == 0) ? v.w : 0.f;
            C.w += (d3 > 0) ? v.w : 0.f;
            *reinterpret_cast<float4*>(orow) = A;   // out[f-1] complete
            orow += Tdim;
        }
    }

    // ---- pair 16: last interior row (f = fs+SEG-1) + upper ghost ----
    acquire(NPAIR - 1);
    A = B; B = C;
    load_row(NR - 2, v, d0, d1, d2, d3);
    if (fs + SEG == Fdim) {   // clip at upper F edge: up-moves stay
        d0 = min(d0, 0); d1 = min(d1, 0); d2 = min(d2, 0); d3 = min(d3, 0);
    }
    // C-part (out[fs+SEG]) belongs to the neighbor block: discard.
    A.x += (d0 < 0) ? v.x : 0.f;  B.x += (d0 == 0) ? v.x : 0.f;
    A.y += (d1 < 0) ? v.y : 0.f;  B.y += (d1 == 0) ? v.y : 0.f;
    A.z += (d2 < 0) ? v.z : 0.f;  B.z += (d2 == 0) ? v.z : 0.f;
    A.w += (d3 < 0) ? v.w : 0.f;  B.w += (d3 == 0) ? v.w : 0.f;
    *reinterpret_cast<float4*>(orow) = A;       // out[fs+SEG-2]
    orow += Tdim;

    if (fs + SEG < Fdim) {   // upper ghost: only its down-moves in B
        load_row(NR - 1, v, d0, d1, d2, d3);
        B.x += (d0 < 0) ? v.x : 0.f;
        B.y += (d1 < 0) ? v.y : 0.f;
        B.z += (d2 < 0) ? v.z : 0.f;
        B.w += (d3 < 0) ? v.w : 0.f;
    }
    *reinterpret_cast<float4*>(orow) = B;       // out[fs+SEG-1] complete
}

extern "C" void kernel_launch(void* const* d_in, const int* in_sizes, int n_in,
                              void* d_out, int out_size) {
    const float* coeffs = (const float*)d_in[0];
    float* out = (float*)d_out;

    dim3 grid(Tdim / 4 / TPB, Bdim, NSEG);   // (16, 16, 8) = 2048 CTAs
    dim3 block(TPB);
    sst_pipe_kernel<<<grid, block>>>(coeffs, out);
}